// round 14
// baseline (speedup 1.0000x reference)
#include <cuda_runtime.h>
#include <cuda_bf16.h>
#include <cstdint>
#include <math.h>

// Problem shapes
#define BB   8
#define NN   512
#define DD   1024
#define HH   16
#define HDIM 64
#define NC   13
#define NM   208          // HH*NC score columns
#define NMP  256          // padded
#define NTOK (BB*NN)      // 4096
#define KTRIP 3072
#define KOUT  640         // 3*208 padded to 640
#define TM    128
#define TN    128

// ================= scratch =================
__device__ float g_Kc[128 * DD];
__device__ float g_Vc[128 * DD];
__device__ float g_part[8 * 128 * DD];
__device__ float g_spart[4 * NTOK * NMP];
__device__ float g_Qeq[64 * DD];
__device__ int   g_cand_idx[BB][16];
__device__ float g_cand_dist[BB][16];
__device__ int   g_K;
__device__ int   g_ego_idx[64];
__device__ int   g_ego_cnt;
__device__ __nv_bfloat16 g_Abf[(size_t)NTOK * KTRIP];
__device__ __nv_bfloat16 g_Mbf[(size_t)BB * NMP * KTRIP];
__device__ __nv_bfloat16 g_Ptbf[(size_t)BB * DD * KOUT];
__device__ __nv_bfloat16 g_AW[(size_t)NTOK * KOUT];

// ================= helpers =================
__device__ __forceinline__ uint32_t smem_u32(const void* p) {
    uint32_t a;
    asm("{ .reg .u64 t; cvta.to.shared.u64 t, %1; cvt.u32.u64 %0, t; }" : "=r"(a) : "l"(p));
    return a;
}
__device__ __forceinline__ void cp16s(uint32_t dst_smem, const void* src) {
    asm volatile("cp.async.cg.shared.global [%0], [%1], 16;" :: "r"(dst_smem), "l"(src));
}
#define CP_COMMIT() asm volatile("cp.async.commit_group;" ::: "memory")
#define CP_WAIT(n)  asm volatile("cp.async.wait_group %0;" :: "n"(n) : "memory")

__device__ __forceinline__ void mma16816(float* c, const uint32_t* a, const uint32_t* b) {
    asm volatile(
        "mma.sync.aligned.m16n8k16.row.col.f32.bf16.bf16.f32 "
        "{%0,%1,%2,%3}, {%4,%5,%6,%7}, {%8,%9}, {%0,%1,%2,%3};"
        : "+f"(c[0]), "+f"(c[1]), "+f"(c[2]), "+f"(c[3])
        : "r"(a[0]), "r"(a[1]), "r"(a[2]), "r"(a[3]), "r"(b[0]), "r"(b[1]));
}
__device__ __forceinline__ void ldsm_x4(uint32_t& r0, uint32_t& r1, uint32_t& r2, uint32_t& r3,
                                        uint32_t addr) {
    asm volatile("ldmatrix.sync.aligned.m8n8.x4.shared.b16 {%0,%1,%2,%3}, [%4];"
                 : "=r"(r0), "=r"(r1), "=r"(r2), "=r"(r3) : "r"(addr));
}
__device__ __forceinline__ unsigned short bfu(__nv_bfloat16 v) {
    return *reinterpret_cast<unsigned short*>(&v);
}
__device__ __forceinline__ void split8(const float4& v0, const float4& v1,
                                       ushort4& hv0, ushort4& hv1,
                                       ushort4& lv0, ushort4& lv1) {
    float x[8] = {v0.x, v0.y, v0.z, v0.w, v1.x, v1.y, v1.z, v1.w};
    unsigned short hs[8], ls[8];
#pragma unroll
    for (int i = 0; i < 8; i++) {
        __nv_bfloat16 h = __float2bfloat16(x[i]);
        __nv_bfloat16 l = __float2bfloat16(x[i] - __bfloat162float(h));
        hs[i] = bfu(h); ls[i] = bfu(l);
    }
    hv0 = make_ushort4(hs[0], hs[1], hs[2], hs[3]);
    hv1 = make_ushort4(hs[4], hs[5], hs[6], hs[7]);
    lv0 = make_ushort4(ls[0], ls[1], ls[2], ls[3]);
    lv1 = make_ushort4(ls[4], ls[5], ls[6], ls[7]);
}

// ======= L1: pack X + candidates + K + ego list + M/P pad zeroing =======
// [0,2048) pack X ; [2048,2056) candidates ; [2056,2440) M pad ; [2440,2472) P pad
__global__ __launch_bounds__(256)
void prep_kernel(const float* __restrict__ tokens,
                 const float* __restrict__ dist,
                 const float* __restrict__ speed,
                 const int* __restrict__ mask_i32,
                 __nv_bfloat16* __restrict__ Abf) {
    __shared__ float d_sh[NN];
    __shared__ unsigned long long red[256];
    __shared__ int scnt;
    int bid = blockIdx.x, t = threadIdx.x;

    if (bid < 2048) {
        int idx = bid * 2048 + t * 8;
        int r = idx >> 10, k = idx & 1023;
        float4 v0 = *(const float4*)&tokens[idx];
        float4 v1 = *(const float4*)&tokens[idx + 4];
        ushort4 hv0, hv1, lv0, lv1;
        split8(v0, v1, hv0, hv1, lv0, lv1);
        size_t base = (size_t)r * KTRIP + k;
        *(ushort4*)&Abf[base]        = hv0; *(ushort4*)&Abf[base + 4]    = hv1;
        *(ushort4*)&Abf[base + 1024] = lv0; *(ushort4*)&Abf[base + 1028] = lv1;
        *(ushort4*)&Abf[base + 2048] = hv0; *(ushort4*)&Abf[base + 2052] = hv1;
        return;
    }
    if (bid >= 2056) {
        if (bid < 2440) {   // M pad rows (m 208..255) -> zero
            int idx = bid - 2056;
            int b = idx / 48, m = 208 + idx % 48;
            uint4* row = (uint4*)(g_Mbf + ((size_t)b * NMP + m) * KTRIP);
            uint4 zz = make_uint4(0, 0, 0, 0);
            for (int q = t; q < 384; q += 256) row[q] = zz;
        } else {            // P pad cols 624..639 -> zero
            int idx = bid - 2440;
            int b = idx >> 2, jq = idx & 3;
            int j = jq * 256 + t;
            uint4* p = (uint4*)(g_Ptbf + ((size_t)b * DD + j) * KOUT + 624);
            p[0] = make_uint4(0, 0, 0, 0);
            p[1] = make_uint4(0, 0, 0, 0);
        }
        return;
    }

    int b = bid - 2048;
    for (int i = t; i < NN; i += 256) d_sh[i] = dist[b * NN + i];
    __syncthreads();
    for (int c = 0; c < NC; c++) {
        unsigned long long best = 0xFFFFFFFFFFFFFFFFull;
        for (int i = t; i < NN; i += 256) {
            unsigned long long key =
                ((unsigned long long)__float_as_uint(d_sh[i]) << 32) | (unsigned)i;
            if (key < best) best = key;
        }
        red[t] = best;
        __syncthreads();
        for (int s = 128; s > 0; s >>= 1) {
            if (t < s && red[t + s] < red[t]) red[t] = red[t + s];
            __syncthreads();
        }
        if (t == 0) {
            int idx = (int)(red[0] & 0xFFFFFFFFu);
            g_cand_idx[b][c]  = idx;
            g_cand_dist[b][c] = __uint_as_float((unsigned)(red[0] >> 32));
            d_sh[idx] = __int_as_float(0x7F800000);
        }
        __syncthreads();
    }
    if (b == 0) {
        int* cnt = (int*)red;
        int c = 0;
        for (int i = t; i < NTOK; i += 256) c += (dist[i] < 20.0f) ? 1 : 0;
        cnt[t] = c;
        __syncthreads();
        for (int s = 128; s > 0; s >>= 1) {
            if (t < s) cnt[t] += cnt[t + s];
            __syncthreads();
        }
        if (t == 0) {
            float avg_density = (float)cnt[0] / (float)NTOK;
            float ssum = 0.f;
            for (int i = 0; i < BB; i++) ssum += speed[i];
            float avg_speed = ssum / (float)BB;
            int K = 8;
            if (avg_speed > 15.0f)  K = (K + 1 < 12) ? K + 1 : 12;
            if (avg_density > 0.5f) K = (K + 1 < 12) ? K + 1 : 12;
            if (K > NN - 1) K = NN - 1;
            g_K = K;
        }
        if (t == 0) scnt = 0;
        __syncthreads();
        for (int i = t; i < NTOK; i += 256) {
            if (mask_i32[i] != 0) {
                int p = atomicAdd(&scnt, 1);
                if (p < 64) g_ego_idx[p] = i;
            }
        }
        __syncthreads();
        if (t == 0) g_ego_cnt = (scnt < 64) ? scnt : 64;
    }
}

// ======= L2: candidate K/V fp32 splitK (inline gather) + ego Qeq workers =======
__global__ __launch_bounds__(256)
void cand_ego_kernel(const float* __restrict__ tokens,
                     const float* __restrict__ Wk, const float* __restrict__ Wv,
                     const float* __restrict__ Weq) {
    __shared__ float As[16][64];
    __shared__ float Ws[16][64];
    __shared__ float4 x4s[256];
    int z = blockIdx.z;
    int t = threadIdx.x;

    if (z < 8) {
        const int LD = DD;
        int kv = z >> 2, ks = z & 3;
        const float* W = kv ? Wv : Wk;
        float* C = g_part + (size_t)z * (128 * DD);

        int tm = t >> 4, tn = t & 15;
        int m0 = blockIdx.y << 6, n0 = blockIdx.x << 6;
        int lrow = t >> 2;
        int lk   = (t & 3) << 2;
        int kbase = ks << 8;
        float acc[4][4];
#pragma unroll
        for (int i = 0; i < 4; i++)
#pragma unroll
            for (int j = 0; j < 4; j++) acc[i][j] = 0.f;

        int gr = m0 + lrow;
        bool valid = gr < BB * NC;
        const float* Ab = tokens;
        if (valid) {
            int b = gr / NC, cc = gr % NC;
            int tok = b * NN + g_cand_idx[b][cc];
            Ab = tokens + (size_t)tok * LD + kbase + lk;
        }
        const float* Wb = W + (size_t)(n0 + lrow) * LD + kbase + lk;

        for (int k0 = 0; k0 < 256; k0 += 16) {
            float4 av = valid ? *(const float4*)(Ab + k0) : make_float4(0, 0, 0, 0);
            float4 wv = *(const float4*)(Wb + k0);
            As[lk + 0][lrow] = av.x; As[lk + 1][lrow] = av.y;
            As[lk + 2][lrow] = av.z; As[lk + 3][lrow] = av.w;
            Ws[lk + 0][lrow] = wv.x; Ws[lk + 1][lrow] = wv.y;
            Ws[lk + 2][lrow] = wv.z; Ws[lk + 3][lrow] = wv.w;
            __syncthreads();
#pragma unroll
            for (int k = 0; k < 16; k++) {
                float a0 = As[k][tm * 4 + 0], a1 = As[k][tm * 4 + 1];
                float a2 = As[k][tm * 4 + 2], a3 = As[k][tm * 4 + 3];
                float w0 = Ws[k][tn * 4 + 0], w1 = Ws[k][tn * 4 + 1];
                float w2 = Ws[k][tn * 4 + 2], w3 = Ws[k][tn * 4 + 3];
                acc[0][0] += a0 * w0; acc[0][1] += a0 * w1; acc[0][2] += a0 * w2; acc[0][3] += a0 * w3;
                acc[1][0] += a1 * w0; acc[1][1] += a1 * w1; acc[1][2] += a1 * w2; acc[1][3] += a1 * w3;
                acc[2][0] += a2 * w0; acc[2][1] += a2 * w1; acc[2][2] += a2 * w2; acc[2][3] += a2 * w3;
                acc[3][0] += a3 * w0; acc[3][1] += a3 * w1; acc[3][2] += a3 * w2; acc[3][3] += a3 * w3;
            }
            __syncthreads();
        }
#pragma unroll
        for (int i = 0; i < 4; i++) {
            float4 v = make_float4(acc[i][0], acc[i][1], acc[i][2], acc[i][3]);
            *(float4*)&C[(size_t)(m0 + tm * 4 + i) * DD + n0 + tn * 4] = v;
        }
        return;
    }

    // ego Qeq workers
    int w = (z - 8) * 32 + blockIdx.y * 16 + blockIdx.x;
    int seg = w & 7;
    int cnt = g_ego_cnt;
    float* comb = (float*)&Ws[0][0];
    for (int e = w >> 3; e < cnt; e += 8) {
        int tok = g_ego_idx[e];
        __syncthreads();
        x4s[t] = ((const float4*)&tokens[(size_t)tok * DD])[t];
        __syncthreads();
        int j  = seg * 128 + (t & 127);
        int kh = t >> 7;
        const float4* wr = (const float4*)&Weq[(size_t)j * DD] + kh * 128;
        const float4* xb = x4s + kh * 128;
        float s0 = 0, s1 = 0, s2 = 0, s3 = 0;
#pragma unroll 8
        for (int k = 0; k < 128; k += 4) {
            float4 a0 = wr[k + 0], b0 = xb[k + 0];
            float4 a1 = wr[k + 1], b1 = xb[k + 1];
            float4 a2 = wr[k + 2], b2 = xb[k + 2];
            float4 a3 = wr[k + 3], b3 = xb[k + 3];
            s0 += a0.x * b0.x + a0.y * b0.y + a0.z * b0.z + a0.w * b0.w;
            s1 += a1.x * b1.x + a1.y * b1.y + a1.z * b1.z + a1.w * b1.w;
            s2 += a2.x * b2.x + a2.y * b2.y + a2.z * b2.z + a2.w * b2.w;
            s3 += a3.x * b3.x + a3.y * b3.y + a3.z * b3.z + a3.w * b3.w;
        }
        comb[t] = (s0 + s1) + (s2 + s3);
        __syncthreads();
        if (kh == 0)
            g_Qeq[(size_t)e * DD + j] = comb[t] + comb[t + 128];
    }
}

// ======= L3: reduce cand splitK partials -> Kc/Vc =======
__global__ void cand_reduce_kernel() {
    int idx = blockIdx.x * 256 + threadIdx.x;
    int kv = idx >> 15;
    int rem = idx & 32767;
    const float4* p = (const float4*)g_part;
    float4 a = p[(size_t)(kv * 4 + 0) * 32768 + rem];
    float4 b = p[(size_t)(kv * 4 + 1) * 32768 + rem];
    float4 c = p[(size_t)(kv * 4 + 2) * 32768 + rem];
    float4 d = p[(size_t)(kv * 4 + 3) * 32768 + rem];
    float4 s = make_float4(a.x + b.x + c.x + d.x, a.y + b.y + c.y + d.y,
                           a.z + b.z + c.z + d.z, a.w + b.w + c.w + d.w);
    float4* dst = (float4*)(kv ? g_Vc : g_Kc);
    dst[rem] = s;
}

// ======= L4: precompute M / P^T — weights staged once, b-loop inside ===
// grid 512: bid>>8 = branch (0=M, 1=P); (bid>>7)&1 = b-group; h=(bid>>3)&15; jc=bid&7
__global__ __launch_bounds__(256)
void mp_pre_kernel(const float* __restrict__ Wq, const float* __restrict__ Wo) {
    __shared__ float wbuf[8448];        // M: [d*129+jl] (64x128) ; P: [jl*66+d] (128x64)
    __shared__ float cv_s[13][65];
    __shared__ float part_s[128][13];
    int bid = blockIdx.x, t = threadIdx.x;
    int branch = bid >> 8;
    int bg = (bid >> 7) & 1;
    int h  = (bid >> 3) & 15;
    int jc = bid & 7;
    int j0 = jc * 128;
    int dh = t >> 7, jl = t & 127;

    if (branch == 0) {
        // stage Wq slice once: wbuf[d*129+jl] = Wq[(h*64+d)*DD + j0+jl]
        for (int q = t; q < 64 * 128; q += 256) {
            int d = q >> 7, jj = q & 127;
            wbuf[d * 129 + jj] = Wq[(size_t)(h * 64 + d) * DD + j0 + jj];
        }
        for (int bb = 0; bb < 4; bb++) {
            int b = bg * 4 + bb;
            __syncthreads();
            for (int q = t; q < 13 * 64; q += 256) {
                int c = q >> 6, d = q & 63;
                cv_s[c][d] = g_Kc[(size_t)(b * NC + c) * DD + h * 64 + d];
            }
            __syncthreads();
            float acc[13];
#pragma unroll
            for (int c = 0; c < 13; c++) acc[c] = 0.f;
#pragma unroll 8
            for (int d = 0; d < 32; d++) {
                int dd = dh * 32 + d;
                float wq = wbuf[dd * 129 + jl];
#pragma unroll
                for (int c = 0; c < 13; c++) acc[c] += wq * cv_s[c][dd];
            }
            if (dh == 1) {
#pragma unroll
                for (int c = 0; c < 13; c++) part_s[jl][c] = acc[c];
            }
            __syncthreads();
            if (dh == 0) {
                int j = j0 + jl;
#pragma unroll
                for (int c = 0; c < 13; c++) {
                    float s = acc[c] + part_s[jl][c];
                    __nv_bfloat16 hh = __float2bfloat16(s);
                    __nv_bfloat16 ll = __float2bfloat16(s - __bfloat162float(hh));
                    __nv_bfloat16* Mrow = g_Mbf + ((size_t)b * NMP + h * 13 + c) * KTRIP;
                    Mrow[j] = hh; Mrow[1024 + j] = hh; Mrow[2048 + j] = ll;
                }
            }
        }
    } else {
        // stage Wo slice once: wbuf[jl*66+d] = Wo[(j0+jl)*DD + h*64+d]
        for (int q = t; q < 128 * 64; q += 256) {
            int jj = q >> 6, d = q & 63;
            wbuf[jj * 66 + d] = Wo[(size_t)(j0 + jj) * DD + h * 64 + d];
        }
        for (int bb = 0; bb < 4; bb++) {
            int b = bg * 4 + bb;
            __syncthreads();
            for (int q = t; q < 13 * 64; q += 256) {
                int c = q >> 6, d = q & 63;
                cv_s[c][d] = g_Vc[(size_t)(b * NC + c) * DD + h * 64 + d];
            }
            __syncthreads();
            float acc[13];
#pragma unroll
            for (int c = 0; c < 13; c++) acc[c] = 0.f;
#pragma unroll 8
            for (int d = 0; d < 32; d++) {
                int dd = dh * 32 + d;
                float wo = wbuf[jl * 66 + dd];
#pragma unroll
                for (int c = 0; c < 13; c++) acc[c] += wo * cv_s[c][dd];
            }
            if (dh == 1) {
#pragma unroll
                for (int c = 0; c < 13; c++) part_s[jl][c] = acc[c];
            }
            __syncthreads();
            if (dh == 0) {
                size_t base = ((size_t)b * DD + j0 + jl) * KOUT;
#pragma unroll
                for (int c = 0; c < 13; c++) {
                    float s = acc[c] + part_s[jl][c];
                    __nv_bfloat16 hh = __float2bfloat16(s);
                    __nv_bfloat16 ll = __float2bfloat16(s - __bfloat162float(hh));
                    int m = h * 13 + c;
                    g_Ptbf[base + m] = hh; g_Ptbf[base + 208 + m] = hh; g_Ptbf[base + 416 + m] = ll;
                }
            }
        }
    }
}

// ======= tensor GEMM machinery =======
#define SPAD 40
#define STG  4
#define ASTG (TM * SPAD * 2)
#define BOFF (STG * ASTG)
#define SMTOT (2 * STG * ASTG)

// L5: scores = X @ M^T  (splitK=4). grid (2, 32, 4)
#define SNCH 24
__global__ void __launch_bounds__(256, 2)
scores_gemm_kernel(const __nv_bfloat16* __restrict__ Abf,
                   const __nv_bfloat16* __restrict__ Mbf) {
    extern __shared__ char smem[];
    uint32_t sb = smem_u32(smem);
    int t = threadIdx.x;
    int wid = t >> 5, lane = t & 31;
    int g = lane >> 2, tg = lane & 3;
    int wm = (wid >> 2) * 64, wn = (wid & 3) * 32;
    int n0 = blockIdx.x * TN;
    int y = blockIdx.y;
    int z = blockIdx.z;
    int m0 = y * TM;
    int kbase = z * SNCH * 32;

    int r0 = t >> 2, s0 = t & 3, r1 = r0 + 64;
    const __nv_bfloat16* Agb = Abf + (size_t)m0 * KTRIP;
    const __nv_bfloat16* Bgb = Mbf + ((size_t)(y >> 2) * NMP + n0) * KTRIP;
    float* C = g_spart + (size_t)z * NTOK * NMP;

    uint32_t aoff = (uint32_t)(((wm + (lane & 7) + (lane & 8)) * SPAD + ((lane >> 4) & 1) * 8) * 2);
    uint32_t boff = (uint32_t)(((wn + (lane & 7) + ((lane >> 4) & 1) * 8) * SPAD + (lane & 8)) * 2);

    float acc[4][4][4];
#pragma unroll
    for (int i = 0; i < 4; i++)
#pragma unroll
        for (int j = 0; j < 4; j++)
#pragma unroll
            for (int q = 0; q < 4; q++) acc[i][j][q] = 0.f;

#pragma unroll
    for (int p = 0; p < STG - 1; p++) {
        uint32_t as = sb + p * ASTG, bs = sb + BOFF + p * ASTG;
        int co = kbase + p * 32 + s0 * 8;
        cp16s(as + (r0 * SPAD + s0 * 8) * 2, Agb + (size_t)r0 * KTRIP + co);
        cp16s(as + (r1 * SPAD + s0 * 8) * 2, Agb + (size_t)r1 * KTRIP + co);
        cp16s(bs + (r0 * SPAD + s0 * 8) * 2, Bgb + (size_t)r0 * KTRIP + co);
        cp16s(bs + (r1 * SPAD + s0 * 8) * 2, Bgb + (size_t)r1 * KTRIP + co);
        CP_COMMIT();
    }
    for (int c = 0; c < SNCH; c++) {
        if (c < SNCH - 2)      { CP_WAIT(2); }
        else if (c < SNCH - 1) { CP_WAIT(1); }
        else                   { CP_WAIT(0); }
        __syncthreads();
        if (c + STG - 1 < SNCH) {
            int ns = (c + STG - 1) & (STG - 1);
            uint32_t as = sb + ns * ASTG, bs = sb + BOFF + ns * ASTG;
            int co = kbase + (c + STG - 1) * 32 + s0 * 8;
            cp16s(as + (r0 * SPAD + s0 * 8) * 2, Agb + (size_t)r0 * KTRIP + co);
            cp16s(as + (r1 * SPAD + s0 * 8) * 2, Agb + (size_t)r1 * KTRIP + co);
            cp16s(bs + (r0 * SPAD + s0 * 8) * 2, Bgb + (size_t)r0 * KTRIP + co);
            cp16s(bs + (r1 * SPAD + s0 * 8) * 2, Bgb + (size_t)r1 * KTRIP + co);
            CP_COMMIT();
        }
        int st = c & (STG - 1);
        uint32_t aB = sb + st * ASTG + aoff;
        uint32_t bB = sb + BOFF + st * ASTG + boff;
#pragma unroll
        for (int kk = 0; kk < 32; kk += 16) {
            uint32_t af[4][4], bfr[2][4];
#pragma unroll
            for (int mi = 0; mi < 4; mi++)
                ldsm_x4(af[mi][0], af[mi][1], af[mi][2], af[mi][3],
                        aB + (uint32_t)((mi * 16 * SPAD + kk) * 2));
            ldsm_x4(bfr[0][0], bfr[0][1], bfr[0][2], bfr[0][3], bB + (uint32_t)(kk * 2));
            ldsm_x4(bfr[1][0], bfr[1][1], bfr[1][2], bfr[1][3],
                    bB + (uint32_t)((16 * SPAD + kk) * 2));
#pragma unroll
            for (int mi = 0; mi < 4; mi++) {
                mma16816(acc[mi][0], af[mi], &bfr[0][0]);
                mma16816(acc[mi][1], af[mi], &bfr[0][2]);
                mma16816(acc[mi][2], af[mi], &bfr[1][0]);
                mma16816(acc[mi][3], af[mi], &bfr[1][2]);
            }
        }
    }
#pragma unroll
    for (int mi = 0; mi < 4; mi++) {
        int row = m0 + wm + mi * 16 + g;
#pragma unroll
        for (int ni = 0; ni < 4; ni++) {
            int col = n0 + wn + ni * 8 + 2 * tg;
            *(float2*)&C[(size_t)row * NMP + col] =
                make_float2(acc[mi][ni][0], acc[mi][ni][1]);
            *(float2*)&C[(size_t)(row + 8) * NMP + col] =
                make_float2(acc[mi][ni][2], acc[mi][ni][3]);
        }
    }
}

// L7: out = attnW @ P^T.  grid (8, 32)
#define ONCH 20
__global__ void __launch_bounds__(256, 2)
out_gemm_kernel(const __nv_bfloat16* __restrict__ AW,
                const __nv_bfloat16* __restrict__ Ptbf,
                float* __restrict__ out) {
    extern __shared__ char smem[];
    uint32_t sb = smem_u32(smem);
    int t = threadIdx.x;
    int wid = t >> 5, lane = t & 31;
    int g = lane >> 2, tg = lane & 3;
    int wm = (wid >> 2) * 64, wn = (wid & 3) * 32;
    int n0 = blockIdx.x * TN;
    int y = blockIdx.y;
    int m0 = y * TM;

    int r0 = t >> 2, s0 = t & 3, r1 = r0 + 64;
    const __nv_bfloat16* Agb = AW + (size_t)m0 * KOUT;
    const __nv_bfloat16* Bgb = Ptbf + ((size_t)(y >> 2) * DD + n0) * KOUT;

    uint32_t aoff = (uint32_t)(((wm + (lane & 7) + (lane & 8)) * SPAD + ((lane >> 4) & 1) * 8) * 2);
    uint32_t boff = (uint32_t)(((wn + (lane & 7) + ((lane >> 4) & 1) * 8) * SPAD + (lane & 8)) * 2);

    float acc[4][4][4];
#pragma unroll
    for (int i = 0; i < 4; i++)
#pragma unroll
        for (int j = 0; j < 4; j++)
#pragma unroll
            for (int q = 0; q < 4; q++) acc[i][j][q] = 0.f;

#pragma unroll
    for (int p = 0; p < STG - 1; p++) {
        uint32_t as = sb + p * ASTG, bs = sb + BOFF + p * ASTG;
        int co = p * 32 + s0 * 8;
        cp16s(as + (r0 * SPAD + s0 * 8) * 2, Agb + (size_t)r0 * KOUT + co);
        cp16s(as + (r1 * SPAD + s0 * 8) * 2, Agb + (size_t)r1 * KOUT + co);
        cp16s(bs + (r0 * SPAD + s0 * 8) * 2, Bgb + (size_t)r0 * KOUT + co);
        cp16s(bs + (r1 * SPAD + s0 * 8) * 2, Bgb + (size_t)r1 * KOUT + co);
        CP_COMMIT();
    }
    for (int c = 0; c < ONCH; c++) {
        if (c < ONCH - 2)      { CP_WAIT(2); }
        else if (c < ONCH - 1) { CP_WAIT(1); }
        else                   { CP_WAIT(0); }
        __syncthreads();
        if (c + STG - 1 < ONCH) {
            int ns = (c + STG - 1) & (STG - 1);
            uint32_t as = sb + ns * ASTG, bs = sb + BOFF + ns * ASTG;
            int co = (c + STG - 1) * 32 + s0 * 8;
            cp16s(as + (r0 * SPAD + s0 * 8) * 2, Agb + (size_t)r0 * KOUT + co);
            cp16s(as + (r1 * SPAD + s0 * 8) * 2, Agb + (size_t)r1 * KOUT + co);
            cp16s(bs + (r0 * SPAD + s0 * 8) * 2, Bgb + (size_t)r0 * KOUT + co);
            cp16s(bs + (r1 * SPAD + s0 * 8) * 2, Bgb + (size_t)r1 * KOUT + co);
            CP_COMMIT();
        }
        int st = c & (STG - 1);
        uint32_t aB = sb + st * ASTG + aoff;
        uint32_t bB = sb + BOFF + st * ASTG + boff;
#pragma unroll
        for (int kk = 0; kk < 32; kk += 16) {
            uint32_t af[4][4], bfr[2][4];
#pragma unroll
            for (int mi = 0; mi < 4; mi++)
                ldsm_x4(af[mi][0], af[mi][1], af[mi][2], af[mi][3],
                        aB + (uint32_t)((mi * 16 * SPAD + kk) * 2));
            ldsm_x4(bfr[0][0], bfr[0][1], bfr[0][2], bfr[0][3], bB + (uint32_t)(kk * 2));
            ldsm_x4(bfr[1][0], bfr[1][1], bfr[1][2], bfr[1][3],
                    bB + (uint32_t)((16 * SPAD + kk) * 2));
#pragma unroll
            for (int mi = 0; mi < 4; mi++) {
                mma16816(acc[mi][0], af[mi], &bfr[0][0]);
                mma16816(acc[mi][1], af[mi], &bfr[0][2]);
                mma16816(acc[mi][2], af[mi], &bfr[1][0]);
                mma16816(acc[mi][3], af[mi], &bfr[1][2]);
            }
        }
    }
#pragma unroll
    for (int mi = 0; mi < 4; mi++) {
        int row = m0 + wm + mi * 16 + g;
#pragma unroll
        for (int ni = 0; ni < 4; ni++) {
            int col = n0 + wn + ni * 8 + 2 * tg;
            *(float2*)&out[(size_t)row * DD + col] =
                make_float2(acc[mi][ni][0], acc[mi][ni][1]);
            *(float2*)&out[(size_t)(row + 8) * DD + col] =
                make_float2(acc[mi][ni][2], acc[mi][ni][3]);
        }
    }
}

// ======= L6: attn — bias MLP + softmax -> packed attn weights =======
__global__ __launch_bounds__(256)
void attn2_kernel(const float* __restrict__ dist,
                  const float* __restrict__ W1, const float* __restrict__ b1,
                  const float* __restrict__ W2, const float* __restrict__ b2) {
    __shared__ __align__(16) float w2_sh[HH][256];
    __shared__ __align__(16) float hid_sh[NC][260];
    __shared__ float qk_sh[NM];
    __shared__ float sc_sh[NM];
    __shared__ float aw_sh[NM];
    __shared__ float dj_sh[NC];
    __shared__ int   sel_sh[NC];
    __shared__ int   ego_sh;

    int tok = blockIdx.x;
    int b = tok >> 9, i = tok & 511;
    int t = threadIdx.x;
    int wid = t >> 5, lane = t & 31;

    if (t == 0) {
        int K = g_K;
        int cnt = 0;
        for (int c = 0; c < NC; c++) {
            int idx = g_cand_idx[b][c];
            int s = (idx != i && cnt < K) ? 1 : 0;
            sel_sh[c] = s;
            cnt += s;
        }
        int e = -1, ec = g_ego_cnt;
        for (int q = 0; q < ec; q++)
            if (g_ego_idx[q] == tok) e = q;
        ego_sh = e;
    }
    if (t < NC) dj_sh[t] = g_cand_dist[b][t];
    {
        float4* w2v = (float4*)w2_sh;
        const float4* w2g = (const float4*)W2;
#pragma unroll
        for (int v = 0; v < 4; v++)
            w2v[t + v * 256] = w2g[t + v * 256];
    }
    if (t < NM) {
        qk_sh[t] = g_spart[(size_t)tok * NMP + t]
                 + g_spart[(size_t)NTOK * NMP + (size_t)tok * NMP + t]
                 + g_spart[2 * (size_t)NTOK * NMP + (size_t)tok * NMP + t]
                 + g_spart[3 * (size_t)NTOK * NMP + (size_t)tok * NMP + t];
    }
    __syncthreads();

    float d_i = dist[tok];
    for (int v = t; v < NC * 256; v += 256) {
        int k = v >> 8, r = v & 255;
        float h = d_i * W1[r * 2] + dj_sh[k] * W1[r * 2 + 1] + b1[r];
        hid_sh[k][r] = fmaxf(h, 0.f);
    }
    __syncthreads();

    int ego = ego_sh;
    for (int p = wid; p < NM; p += 8) {
        int h = p / NC, c = p - h * NC;
        float4 ha = *(const float4*)&hid_sh[c][lane * 4];
        float4 wa = *(const float4*)&w2_sh[h][lane * 4];
        float4 hb = *(const float4*)&hid_sh[c][128 + lane * 4];
        float4 wb = *(const float4*)&w2_sh[h][128 + lane * 4];
        float part = ha.x * wa.x + ha.y * wa.y + ha.z * wa.z + ha.w * wa.w
                   + hb.x * wb.x + hb.y * wb.y + hb.z * wb.z + hb.w * wb.w;
        if (ego >= 0) {
            float2 qv = *(const float2*)&g_Qeq[(size_t)ego * DD + h * HDIM + lane * 2];
            float2 kv = *(const float2*)&g_Kc[(size_t)(b * NC + c) * DD + h * HDIM + lane * 2];
            part += 0.125f * (qv.x * kv.x + qv.y * kv.y);
        }
#pragma unroll
        for (int s = 16; s > 0; s >>= 1)
            part += __shfl_xor_sync(0xFFFFFFFFu, part, s);
        if (lane == 0) {
            float qk = (ego >= 0) ? 0.f : 0.125f * qk_sh[p];
            sc_sh[p] = part + qk + b2[h];
        }
    }
    __syncthreads();

    if (t < HH) {
        float mx = -1e30f;
        for (int c = 0; c < NC; c++)
            if (sel_sh[c]) mx = fmaxf(mx, sc_sh[t * NC + c]);
        float sm = 0.f;
        float ev[NC];
#pragma unroll
        for (int c = 0; c < NC; c++) {
            float e = sel_sh[c] ? expf(sc_sh[t * NC + c] - mx) : 0.f;
            ev[c] = e; sm += e;
        }
        float inv = 1.f / sm;
#pragma unroll
        for (int c = 0; c < NC; c++) aw_sh[t * NC + c] = ev[c] * inv;
    }
    __syncthreads();

    size_t base = (size_t)tok * KOUT;
    if (t < NM) {
        float w = aw_sh[t];
        __nv_bfloat16 hh = __float2bfloat16(w);
        __nv_bfloat16 ll = __float2bfloat16(w - __bfloat162float(hh));
        g_AW[base + t] = hh;
        g_AW[base + 208 + t] = ll;
        g_AW[base + 416 + t] = hh;
    } else if (t < 224) {
        g_AW[base + 416 + t] = __float2bfloat16(0.f);
    }
}

// ================= launch =================
extern "C" void kernel_launch(void* const* d_in, const int* in_sizes, int n_in,
                              void* d_out, int out_size) {
    const float* tokens = (const float*)d_in[0];
    const float* dist   = (const float*)d_in[1];
    const int*   mask   = (const int*)d_in[2];
    const float* speed  = (const float*)d_in[3];
    const float* Wq     = (const float*)d_in[4];
    const float* Wk     = (const float*)d_in[5];
    const float* Wv     = (const float*)d_in[6];
    const float* Weq    = (const float*)d_in[7];
    const float* Wo     = (const float*)d_in[8];
    const float* W1     = (const float*)d_in[9];
    const float* b1     = (const float*)d_in[10];
    const float* W2     = (const float*)d_in[11];
    const float* b2     = (const float*)d_in[12];
    float*       out    = (float*)d_out;

    __nv_bfloat16 *pAbf, *pMbf, *pPtbf, *pAW;
    cudaGetSymbolAddress((void**)&pAbf,  g_Abf);
    cudaGetSymbolAddress((void**)&pMbf,  g_Mbf);
    cudaGetSymbolAddress((void**)&pPtbf, g_Ptbf);
    cudaGetSymbolAddress((void**)&pAW,   g_AW);

    cudaFuncSetAttribute(scores_gemm_kernel, cudaFuncAttributeMaxDynamicSharedMemorySize, SMTOT);
    cudaFuncSetAttribute(out_gemm_kernel,    cudaFuncAttributeMaxDynamicSharedMemorySize, SMTOT);

    // 1: pack X + candidates + K + ego list + M/P padding
    prep_kernel<<<2472, 256>>>(tokens, dist, speed, mask, pAbf);
    // 2: candidate K/V (fp32 splitK) + ego Qeq rows
    cand_ego_kernel<<<dim3(16, 2, 10), 256>>>(tokens, Wk, Wv, Weq);
    // 3: reduce K/V partials
    cand_reduce_kernel<<<256, 256>>>();
    // 4: M / P^T precompute + pack, b-loop amortized (PROFILED SLOT)
    mp_pre_kernel<<<512, 256>>>(Wq, Wo);
    // 5: scores GEMM (splitK=4)
    scores_gemm_kernel<<<dim3(2, 32, 4), 256, SMTOT>>>(pAbf, pMbf);
    // 6: bias + softmax -> packed attn weights
    attn2_kernel<<<NTOK, 256>>>(dist, W1, b1, W2, b2);
    // 7: out = attnW @ P^T
    out_gemm_kernel<<<dim3(8, 32), 256, SMTOT>>>(pAW, pPtbf, out);
}

// round 15
// speedup vs baseline: 1.7576x; 1.7576x over previous
#include <cuda_runtime.h>
#include <cuda_bf16.h>
#include <cstdint>
#include <math.h>

// Problem shapes
#define BB   8
#define NN   512
#define DD   1024
#define HH   16
#define HDIM 64
#define NC   13
#define NM   208          // HH*NC score columns
#define NMP  256          // padded
#define NTOK (BB*NN)      // 4096
#define KTRIP 3072
#define KOUT  640         // 3*208=624 padded to 640 (triplet layout k=3m+copy)
#define TM    128
#define TN    128

// ================= scratch =================
__device__ float g_Kc[128 * DD];
__device__ float g_Vc[128 * DD];
__device__ float g_part[8 * 128 * DD];
__device__ float g_spart[4 * NTOK * NMP];
__device__ float g_Qeq[64 * DD];
__device__ int   g_cand_idx[BB][16];
__device__ float g_cand_dist[BB][16];
__device__ int   g_K;
__device__ int   g_ego_idx[64];
__device__ int   g_ego_cnt;
__device__ __nv_bfloat16 g_Abf[(size_t)NTOK * KTRIP];
__device__ __nv_bfloat16 g_Mbf[(size_t)BB * NMP * KTRIP];
__device__ __nv_bfloat16 g_Ptbf[(size_t)BB * DD * KOUT];
__device__ __nv_bfloat16 g_AW[(size_t)NTOK * KOUT];

// ================= helpers =================
__device__ __forceinline__ uint32_t smem_u32(const void* p) {
    uint32_t a;
    asm("{ .reg .u64 t; cvta.to.shared.u64 t, %1; cvt.u32.u64 %0, t; }" : "=r"(a) : "l"(p));
    return a;
}
__device__ __forceinline__ void cp16s(uint32_t dst_smem, const void* src) {
    asm volatile("cp.async.cg.shared.global [%0], [%1], 16;" :: "r"(dst_smem), "l"(src));
}
#define CP_COMMIT() asm volatile("cp.async.commit_group;" ::: "memory")
#define CP_WAIT(n)  asm volatile("cp.async.wait_group %0;" :: "n"(n) : "memory")

__device__ __forceinline__ void mma16816(float* c, const uint32_t* a, const uint32_t* b) {
    asm volatile(
        "mma.sync.aligned.m16n8k16.row.col.f32.bf16.bf16.f32 "
        "{%0,%1,%2,%3}, {%4,%5,%6,%7}, {%8,%9}, {%0,%1,%2,%3};"
        : "+f"(c[0]), "+f"(c[1]), "+f"(c[2]), "+f"(c[3])
        : "r"(a[0]), "r"(a[1]), "r"(a[2]), "r"(a[3]), "r"(b[0]), "r"(b[1]));
}
__device__ __forceinline__ void ldsm_x4(uint32_t& r0, uint32_t& r1, uint32_t& r2, uint32_t& r3,
                                        uint32_t addr) {
    asm volatile("ldmatrix.sync.aligned.m8n8.x4.shared.b16 {%0,%1,%2,%3}, [%4];"
                 : "=r"(r0), "=r"(r1), "=r"(r2), "=r"(r3) : "r"(addr));
}
__device__ __forceinline__ unsigned short bfu(__nv_bfloat16 v) {
    return *reinterpret_cast<unsigned short*>(&v);
}
__device__ __forceinline__ void split8(const float4& v0, const float4& v1,
                                       ushort4& hv0, ushort4& hv1,
                                       ushort4& lv0, ushort4& lv1) {
    float x[8] = {v0.x, v0.y, v0.z, v0.w, v1.x, v1.y, v1.z, v1.w};
    unsigned short hs[8], ls[8];
#pragma unroll
    for (int i = 0; i < 8; i++) {
        __nv_bfloat16 h = __float2bfloat16(x[i]);
        __nv_bfloat16 l = __float2bfloat16(x[i] - __bfloat162float(h));
        hs[i] = bfu(h); ls[i] = bfu(l);
    }
    hv0 = make_ushort4(hs[0], hs[1], hs[2], hs[3]);
    hv1 = make_ushort4(hs[4], hs[5], hs[6], hs[7]);
    lv0 = make_ushort4(ls[0], ls[1], ls[2], ls[3]);
    lv1 = make_ushort4(ls[4], ls[5], ls[6], ls[7]);
}

// ======= L1: pack X + candidates + K + ego list + M/P pad zeroing =======
// [0,2048) pack X ; [2048,2056) candidates ; [2056,2440) M pad ; [2440,2472) P pad
__global__ __launch_bounds__(256)
void prep_kernel(const float* __restrict__ tokens,
                 const float* __restrict__ dist,
                 const float* __restrict__ speed,
                 const int* __restrict__ mask_i32,
                 __nv_bfloat16* __restrict__ Abf) {
    __shared__ float d_sh[NN];
    __shared__ unsigned long long red[256];
    __shared__ int scnt;
    int bid = blockIdx.x, t = threadIdx.x;

    if (bid < 2048) {
        int idx = bid * 2048 + t * 8;
        int r = idx >> 10, k = idx & 1023;
        float4 v0 = *(const float4*)&tokens[idx];
        float4 v1 = *(const float4*)&tokens[idx + 4];
        ushort4 hv0, hv1, lv0, lv1;
        split8(v0, v1, hv0, hv1, lv0, lv1);
        size_t base = (size_t)r * KTRIP + k;
        *(ushort4*)&Abf[base]        = hv0; *(ushort4*)&Abf[base + 4]    = hv1;
        *(ushort4*)&Abf[base + 1024] = lv0; *(ushort4*)&Abf[base + 1028] = lv1;
        *(ushort4*)&Abf[base + 2048] = hv0; *(ushort4*)&Abf[base + 2052] = hv1;
        return;
    }
    if (bid >= 2056) {
        if (bid < 2440) {   // M pad rows (m 208..255) -> zero
            int idx = bid - 2056;
            int b = idx / 48, m = 208 + idx % 48;
            uint4* row = (uint4*)(g_Mbf + ((size_t)b * NMP + m) * KTRIP);
            uint4 zz = make_uint4(0, 0, 0, 0);
            for (int q = t; q < 384; q += 256) row[q] = zz;
        } else {            // P pad cols 624..639 -> zero
            int idx = bid - 2440;
            int b = idx >> 2, jq = idx & 3;
            int j = jq * 256 + t;
            uint4* p = (uint4*)(g_Ptbf + ((size_t)b * DD + j) * KOUT + 624);
            p[0] = make_uint4(0, 0, 0, 0);
            p[1] = make_uint4(0, 0, 0, 0);
        }
        return;
    }

    int b = bid - 2048;
    for (int i = t; i < NN; i += 256) d_sh[i] = dist[b * NN + i];
    __syncthreads();
    for (int c = 0; c < NC; c++) {
        unsigned long long best = 0xFFFFFFFFFFFFFFFFull;
        for (int i = t; i < NN; i += 256) {
            unsigned long long key =
                ((unsigned long long)__float_as_uint(d_sh[i]) << 32) | (unsigned)i;
            if (key < best) best = key;
        }
        red[t] = best;
        __syncthreads();
        for (int s = 128; s > 0; s >>= 1) {
            if (t < s && red[t + s] < red[t]) red[t] = red[t + s];
            __syncthreads();
        }
        if (t == 0) {
            int idx = (int)(red[0] & 0xFFFFFFFFu);
            g_cand_idx[b][c]  = idx;
            g_cand_dist[b][c] = __uint_as_float((unsigned)(red[0] >> 32));
            d_sh[idx] = __int_as_float(0x7F800000);
        }
        __syncthreads();
    }
    if (b == 0) {
        int* cnt = (int*)red;
        int c = 0;
        for (int i = t; i < NTOK; i += 256) c += (dist[i] < 20.0f) ? 1 : 0;
        cnt[t] = c;
        __syncthreads();
        for (int s = 128; s > 0; s >>= 1) {
            if (t < s) cnt[t] += cnt[t + s];
            __syncthreads();
        }
        if (t == 0) {
            float avg_density = (float)cnt[0] / (float)NTOK;
            float ssum = 0.f;
            for (int i = 0; i < BB; i++) ssum += speed[i];
            float avg_speed = ssum / (float)BB;
            int K = 8;
            if (avg_speed > 15.0f)  K = (K + 1 < 12) ? K + 1 : 12;
            if (avg_density > 0.5f) K = (K + 1 < 12) ? K + 1 : 12;
            if (K > NN - 1) K = NN - 1;
            g_K = K;
        }
        if (t == 0) scnt = 0;
        __syncthreads();
        for (int i = t; i < NTOK; i += 256) {
            if (mask_i32[i] != 0) {
                int p = atomicAdd(&scnt, 1);
                if (p < 64) g_ego_idx[p] = i;
            }
        }
        __syncthreads();
        if (t == 0) g_ego_cnt = (scnt < 64) ? scnt : 64;
    }
}

// ======= L2: candidate K/V fp32 splitK (inline gather) + ego Qeq workers =======
__global__ __launch_bounds__(256)
void cand_ego_kernel(const float* __restrict__ tokens,
                     const float* __restrict__ Wk, const float* __restrict__ Wv,
                     const float* __restrict__ Weq) {
    __shared__ float As[16][64];
    __shared__ float Ws[16][64];
    __shared__ float4 x4s[256];
    int z = blockIdx.z;
    int t = threadIdx.x;

    if (z < 8) {
        const int LD = DD;
        int kv = z >> 2, ks = z & 3;
        const float* W = kv ? Wv : Wk;
        float* C = g_part + (size_t)z * (128 * DD);

        int tm = t >> 4, tn = t & 15;
        int m0 = blockIdx.y << 6, n0 = blockIdx.x << 6;
        int lrow = t >> 2;
        int lk   = (t & 3) << 2;
        int kbase = ks << 8;
        float acc[4][4];
#pragma unroll
        for (int i = 0; i < 4; i++)
#pragma unroll
            for (int j = 0; j < 4; j++) acc[i][j] = 0.f;

        int gr = m0 + lrow;
        bool valid = gr < BB * NC;
        const float* Ab = tokens;
        if (valid) {
            int b = gr / NC, cc = gr % NC;
            int tok = b * NN + g_cand_idx[b][cc];
            Ab = tokens + (size_t)tok * LD + kbase + lk;
        }
        const float* Wb = W + (size_t)(n0 + lrow) * LD + kbase + lk;

        for (int k0 = 0; k0 < 256; k0 += 16) {
            float4 av = valid ? *(const float4*)(Ab + k0) : make_float4(0, 0, 0, 0);
            float4 wv = *(const float4*)(Wb + k0);
            As[lk + 0][lrow] = av.x; As[lk + 1][lrow] = av.y;
            As[lk + 2][lrow] = av.z; As[lk + 3][lrow] = av.w;
            Ws[lk + 0][lrow] = wv.x; Ws[lk + 1][lrow] = wv.y;
            Ws[lk + 2][lrow] = wv.z; Ws[lk + 3][lrow] = wv.w;
            __syncthreads();
#pragma unroll
            for (int k = 0; k < 16; k++) {
                float a0 = As[k][tm * 4 + 0], a1 = As[k][tm * 4 + 1];
                float a2 = As[k][tm * 4 + 2], a3 = As[k][tm * 4 + 3];
                float w0 = Ws[k][tn * 4 + 0], w1 = Ws[k][tn * 4 + 1];
                float w2 = Ws[k][tn * 4 + 2], w3 = Ws[k][tn * 4 + 3];
                acc[0][0] += a0 * w0; acc[0][1] += a0 * w1; acc[0][2] += a0 * w2; acc[0][3] += a0 * w3;
                acc[1][0] += a1 * w0; acc[1][1] += a1 * w1; acc[1][2] += a1 * w2; acc[1][3] += a1 * w3;
                acc[2][0] += a2 * w0; acc[2][1] += a2 * w1; acc[2][2] += a2 * w2; acc[2][3] += a2 * w3;
                acc[3][0] += a3 * w0; acc[3][1] += a3 * w1; acc[3][2] += a3 * w2; acc[3][3] += a3 * w3;
            }
            __syncthreads();
        }
#pragma unroll
        for (int i = 0; i < 4; i++) {
            float4 v = make_float4(acc[i][0], acc[i][1], acc[i][2], acc[i][3]);
            *(float4*)&C[(size_t)(m0 + tm * 4 + i) * DD + n0 + tn * 4] = v;
        }
        return;
    }

    // ego Qeq workers
    int w = (z - 8) * 32 + blockIdx.y * 16 + blockIdx.x;
    int seg = w & 7;
    int cnt = g_ego_cnt;
    float* comb = (float*)&Ws[0][0];
    for (int e = w >> 3; e < cnt; e += 8) {
        int tok = g_ego_idx[e];
        __syncthreads();
        x4s[t] = ((const float4*)&tokens[(size_t)tok * DD])[t];
        __syncthreads();
        int j  = seg * 128 + (t & 127);
        int kh = t >> 7;
        const float4* wr = (const float4*)&Weq[(size_t)j * DD] + kh * 128;
        const float4* xb = x4s + kh * 128;
        float s0 = 0, s1 = 0, s2 = 0, s3 = 0;
#pragma unroll 8
        for (int k = 0; k < 128; k += 4) {
            float4 a0 = wr[k + 0], b0 = xb[k + 0];
            float4 a1 = wr[k + 1], b1 = xb[k + 1];
            float4 a2 = wr[k + 2], b2 = xb[k + 2];
            float4 a3 = wr[k + 3], b3 = xb[k + 3];
            s0 += a0.x * b0.x + a0.y * b0.y + a0.z * b0.z + a0.w * b0.w;
            s1 += a1.x * b1.x + a1.y * b1.y + a1.z * b1.z + a1.w * b1.w;
            s2 += a2.x * b2.x + a2.y * b2.y + a2.z * b2.z + a2.w * b2.w;
            s3 += a3.x * b3.x + a3.y * b3.y + a3.z * b3.z + a3.w * b3.w;
        }
        comb[t] = (s0 + s1) + (s2 + s3);
        __syncthreads();
        if (kh == 0)
            g_Qeq[(size_t)e * DD + j] = comb[t] + comb[t + 128];
    }
}

// ======= L3: reduce cand splitK partials -> Kc/Vc =======
__global__ void cand_reduce_kernel() {
    int idx = blockIdx.x * 256 + threadIdx.x;
    int kv = idx >> 15;
    int rem = idx & 32767;
    const float4* p = (const float4*)g_part;
    float4 a = p[(size_t)(kv * 4 + 0) * 32768 + rem];
    float4 b = p[(size_t)(kv * 4 + 1) * 32768 + rem];
    float4 c = p[(size_t)(kv * 4 + 2) * 32768 + rem];
    float4 d = p[(size_t)(kv * 4 + 3) * 32768 + rem];
    float4 s = make_float4(a.x + b.x + c.x + d.x, a.y + b.y + c.y + d.y,
                           a.z + b.z + c.z + d.z, a.w + b.w + c.w + d.w);
    float4* dst = (float4*)(kv ? g_Vc : g_Kc);
    dst[rem] = s;
}

// ======= L4: precompute M / P^T (R13 structure; P uses triplet layout) ===
// grid 2048: [0,1024) M-compute (b,h,jc); [1024,2048) P-compute
__global__ __launch_bounds__(256)
void mp_pre_kernel(const float* __restrict__ Wq, const float* __restrict__ Wo) {
    __shared__ float cv_s[13][65];
    __shared__ float part_s[128][13];
    __shared__ float wo_s[128][65];
    int bid = blockIdx.x, t = threadIdx.x;

    if (bid < 1024) {   // ---- M: M[j,(h,c)] = sum_d Wq[h64+d, j]*Kc[b,c,h64+d]
        int b = bid >> 7, h = (bid >> 3) & 15, jc = bid & 7;
        int j0 = jc * 128;
        for (int idx = t; idx < 13 * 64; idx += 256) {
            int c = idx >> 6, d = idx & 63;
            cv_s[c][d] = g_Kc[(size_t)(b * NC + c) * DD + h * 64 + d];
        }
        __syncthreads();
        int dh = t >> 7, jl = t & 127;
        const float* wcol = Wq + (size_t)(h * 64 + dh * 32) * DD + j0 + jl;
        float acc[13];
#pragma unroll
        for (int c = 0; c < 13; c++) acc[c] = 0.f;
#pragma unroll 8
        for (int d = 0; d < 32; d++) {
            float wq = wcol[(size_t)d * DD];
            int dd = dh * 32 + d;
#pragma unroll
            for (int c = 0; c < 13; c++) acc[c] += wq * cv_s[c][dd];
        }
        if (dh == 1) {
#pragma unroll
            for (int c = 0; c < 13; c++) part_s[jl][c] = acc[c];
        }
        __syncthreads();
        if (dh == 0) {
            int j = j0 + jl;
#pragma unroll
            for (int c = 0; c < 13; c++) {
                float s = acc[c] + part_s[jl][c];
                __nv_bfloat16 hh = __float2bfloat16(s);
                __nv_bfloat16 ll = __float2bfloat16(s - __bfloat162float(hh));
                __nv_bfloat16* Mrow = g_Mbf + ((size_t)b * NMP + h * 13 + c) * KTRIP;
                Mrow[j] = hh; Mrow[1024 + j] = hh; Mrow[2048 + j] = ll;
            }
        }
        return;
    }
    // ---- P^T (triplet k-layout: k = 3*m + copy, copies [hi, hi, lo])
    {
        int idx = bid - 1024;
        int b = idx >> 7, h = (idx >> 3) & 15, jc = idx & 7;
        int j0 = jc * 128;
        for (int q = t; q < 128 * 64; q += 256) {
            int jl = q >> 6, d = q & 63;
            wo_s[jl][d] = Wo[(size_t)(j0 + jl) * DD + h * 64 + d];
        }
        for (int q = t; q < 13 * 64; q += 256) {
            int c = q >> 6, d = q & 63;
            cv_s[c][d] = g_Vc[(size_t)(b * NC + c) * DD + h * 64 + d];
        }
        __syncthreads();
        int dh = t >> 7, jl = t & 127;
        float acc[13];
#pragma unroll
        for (int c = 0; c < 13; c++) acc[c] = 0.f;
#pragma unroll 8
        for (int d = 0; d < 32; d++) {
            int dd = dh * 32 + d;
            float wo = wo_s[jl][dd];
#pragma unroll
            for (int c = 0; c < 13; c++) acc[c] += wo * cv_s[c][dd];
        }
        if (dh == 1) {
#pragma unroll
            for (int c = 0; c < 13; c++) part_s[jl][c] = acc[c];
        }
        __syncthreads();
        if (dh == 0) {
            size_t base = ((size_t)b * DD + j0 + jl) * KOUT;
#pragma unroll
            for (int c = 0; c < 13; c++) {
                float s = acc[c] + part_s[jl][c];
                __nv_bfloat16 hh = __float2bfloat16(s);
                __nv_bfloat16 ll = __float2bfloat16(s - __bfloat162float(hh));
                int m = h * 13 + c;
                g_Ptbf[base + 3 * m]     = hh;   // contiguous 78B run per j-row
                g_Ptbf[base + 3 * m + 1] = hh;
                g_Ptbf[base + 3 * m + 2] = ll;
            }
        }
    }
}

// ======= tensor GEMM machinery =======
#define SPAD 40
#define STG  4
#define ASTG (TM * SPAD * 2)
#define BOFF (STG * ASTG)
#define SMTOT (2 * STG * ASTG)

// L5: scores = X @ M^T  (splitK=4). grid (2, 32, 4)
#define SNCH 24
__global__ void __launch_bounds__(256, 2)
scores_gemm_kernel(const __nv_bfloat16* __restrict__ Abf,
                   const __nv_bfloat16* __restrict__ Mbf) {
    extern __shared__ char smem[];
    uint32_t sb = smem_u32(smem);
    int t = threadIdx.x;
    int wid = t >> 5, lane = t & 31;
    int g = lane >> 2, tg = lane & 3;
    int wm = (wid >> 2) * 64, wn = (wid & 3) * 32;
    int n0 = blockIdx.x * TN;
    int y = blockIdx.y;
    int z = blockIdx.z;
    int m0 = y * TM;
    int kbase = z * SNCH * 32;

    int r0 = t >> 2, s0 = t & 3, r1 = r0 + 64;
    const __nv_bfloat16* Agb = Abf + (size_t)m0 * KTRIP;
    const __nv_bfloat16* Bgb = Mbf + ((size_t)(y >> 2) * NMP + n0) * KTRIP;
    float* C = g_spart + (size_t)z * NTOK * NMP;

    uint32_t aoff = (uint32_t)(((wm + (lane & 7) + (lane & 8)) * SPAD + ((lane >> 4) & 1) * 8) * 2);
    uint32_t boff = (uint32_t)(((wn + (lane & 7) + ((lane >> 4) & 1) * 8) * SPAD + (lane & 8)) * 2);

    float acc[4][4][4];
#pragma unroll
    for (int i = 0; i < 4; i++)
#pragma unroll
        for (int j = 0; j < 4; j++)
#pragma unroll
            for (int q = 0; q < 4; q++) acc[i][j][q] = 0.f;

#pragma unroll
    for (int p = 0; p < STG - 1; p++) {
        uint32_t as = sb + p * ASTG, bs = sb + BOFF + p * ASTG;
        int co = kbase + p * 32 + s0 * 8;
        cp16s(as + (r0 * SPAD + s0 * 8) * 2, Agb + (size_t)r0 * KTRIP + co);
        cp16s(as + (r1 * SPAD + s0 * 8) * 2, Agb + (size_t)r1 * KTRIP + co);
        cp16s(bs + (r0 * SPAD + s0 * 8) * 2, Bgb + (size_t)r0 * KTRIP + co);
        cp16s(bs + (r1 * SPAD + s0 * 8) * 2, Bgb + (size_t)r1 * KTRIP + co);
        CP_COMMIT();
    }
    for (int c = 0; c < SNCH; c++) {
        if (c < SNCH - 2)      { CP_WAIT(2); }
        else if (c < SNCH - 1) { CP_WAIT(1); }
        else                   { CP_WAIT(0); }
        __syncthreads();
        if (c + STG - 1 < SNCH) {
            int ns = (c + STG - 1) & (STG - 1);
            uint32_t as = sb + ns * ASTG, bs = sb + BOFF + ns * ASTG;
            int co = kbase + (c + STG - 1) * 32 + s0 * 8;
            cp16s(as + (r0 * SPAD + s0 * 8) * 2, Agb + (size_t)r0 * KTRIP + co);
            cp16s(as + (r1 * SPAD + s0 * 8) * 2, Agb + (size_t)r1 * KTRIP + co);
            cp16s(bs + (r0 * SPAD + s0 * 8) * 2, Bgb + (size_t)r0 * KTRIP + co);
            cp16s(bs + (r1 * SPAD + s0 * 8) * 2, Bgb + (size_t)r1 * KTRIP + co);
            CP_COMMIT();
        }
        int st = c & (STG - 1);
        uint32_t aB = sb + st * ASTG + aoff;
        uint32_t bB = sb + BOFF + st * ASTG + boff;
#pragma unroll
        for (int kk = 0; kk < 32; kk += 16) {
            uint32_t af[4][4], bfr[2][4];
#pragma unroll
            for (int mi = 0; mi < 4; mi++)
                ldsm_x4(af[mi][0], af[mi][1], af[mi][2], af[mi][3],
                        aB + (uint32_t)((mi * 16 * SPAD + kk) * 2));
            ldsm_x4(bfr[0][0], bfr[0][1], bfr[0][2], bfr[0][3], bB + (uint32_t)(kk * 2));
            ldsm_x4(bfr[1][0], bfr[1][1], bfr[1][2], bfr[1][3],
                    bB + (uint32_t)((16 * SPAD + kk) * 2));
#pragma unroll
            for (int mi = 0; mi < 4; mi++) {
                mma16816(acc[mi][0], af[mi], &bfr[0][0]);
                mma16816(acc[mi][1], af[mi], &bfr[0][2]);
                mma16816(acc[mi][2], af[mi], &bfr[1][0]);
                mma16816(acc[mi][3], af[mi], &bfr[1][2]);
            }
        }
    }
#pragma unroll
    for (int mi = 0; mi < 4; mi++) {
        int row = m0 + wm + mi * 16 + g;
#pragma unroll
        for (int ni = 0; ni < 4; ni++) {
            int col = n0 + wn + ni * 8 + 2 * tg;
            *(float2*)&C[(size_t)row * NMP + col] =
                make_float2(acc[mi][ni][0], acc[mi][ni][1]);
            *(float2*)&C[(size_t)(row + 8) * NMP + col] =
                make_float2(acc[mi][ni][2], acc[mi][ni][3]);
        }
    }
}

// L7: out = attnW @ P^T.  grid (8, 32)
#define ONCH 20
__global__ void __launch_bounds__(256, 2)
out_gemm_kernel(const __nv_bfloat16* __restrict__ AW,
                const __nv_bfloat16* __restrict__ Ptbf,
                float* __restrict__ out) {
    extern __shared__ char smem[];
    uint32_t sb = smem_u32(smem);
    int t = threadIdx.x;
    int wid = t >> 5, lane = t & 31;
    int g = lane >> 2, tg = lane & 3;
    int wm = (wid >> 2) * 64, wn = (wid & 3) * 32;
    int n0 = blockIdx.x * TN;
    int y = blockIdx.y;
    int m0 = y * TM;

    int r0 = t >> 2, s0 = t & 3, r1 = r0 + 64;
    const __nv_bfloat16* Agb = AW + (size_t)m0 * KOUT;
    const __nv_bfloat16* Bgb = Ptbf + ((size_t)(y >> 2) * DD + n0) * KOUT;

    uint32_t aoff = (uint32_t)(((wm + (lane & 7) + (lane & 8)) * SPAD + ((lane >> 4) & 1) * 8) * 2);
    uint32_t boff = (uint32_t)(((wn + (lane & 7) + ((lane >> 4) & 1) * 8) * SPAD + (lane & 8)) * 2);

    float acc[4][4][4];
#pragma unroll
    for (int i = 0; i < 4; i++)
#pragma unroll
        for (int j = 0; j < 4; j++)
#pragma unroll
            for (int q = 0; q < 4; q++) acc[i][j][q] = 0.f;

#pragma unroll
    for (int p = 0; p < STG - 1; p++) {
        uint32_t as = sb + p * ASTG, bs = sb + BOFF + p * ASTG;
        int co = p * 32 + s0 * 8;
        cp16s(as + (r0 * SPAD + s0 * 8) * 2, Agb + (size_t)r0 * KOUT + co);
        cp16s(as + (r1 * SPAD + s0 * 8) * 2, Agb + (size_t)r1 * KOUT + co);
        cp16s(bs + (r0 * SPAD + s0 * 8) * 2, Bgb + (size_t)r0 * KOUT + co);
        cp16s(bs + (r1 * SPAD + s0 * 8) * 2, Bgb + (size_t)r1 * KOUT + co);
        CP_COMMIT();
    }
    for (int c = 0; c < ONCH; c++) {
        if (c < ONCH - 2)      { CP_WAIT(2); }
        else if (c < ONCH - 1) { CP_WAIT(1); }
        else                   { CP_WAIT(0); }
        __syncthreads();
        if (c + STG - 1 < ONCH) {
            int ns = (c + STG - 1) & (STG - 1);
            uint32_t as = sb + ns * ASTG, bs = sb + BOFF + ns * ASTG;
            int co = (c + STG - 1) * 32 + s0 * 8;
            cp16s(as + (r0 * SPAD + s0 * 8) * 2, Agb + (size_t)r0 * KOUT + co);
            cp16s(as + (r1 * SPAD + s0 * 8) * 2, Agb + (size_t)r1 * KOUT + co);
            cp16s(bs + (r0 * SPAD + s0 * 8) * 2, Bgb + (size_t)r0 * KOUT + co);
            cp16s(bs + (r1 * SPAD + s0 * 8) * 2, Bgb + (size_t)r1 * KOUT + co);
            CP_COMMIT();
        }
        int st = c & (STG - 1);
        uint32_t aB = sb + st * ASTG + aoff;
        uint32_t bB = sb + BOFF + st * ASTG + boff;
#pragma unroll
        for (int kk = 0; kk < 32; kk += 16) {
            uint32_t af[4][4], bfr[2][4];
#pragma unroll
            for (int mi = 0; mi < 4; mi++)
                ldsm_x4(af[mi][0], af[mi][1], af[mi][2], af[mi][3],
                        aB + (uint32_t)((mi * 16 * SPAD + kk) * 2));
            ldsm_x4(bfr[0][0], bfr[0][1], bfr[0][2], bfr[0][3], bB + (uint32_t)(kk * 2));
            ldsm_x4(bfr[1][0], bfr[1][1], bfr[1][2], bfr[1][3],
                    bB + (uint32_t)((16 * SPAD + kk) * 2));
#pragma unroll
            for (int mi = 0; mi < 4; mi++) {
                mma16816(acc[mi][0], af[mi], &bfr[0][0]);
                mma16816(acc[mi][1], af[mi], &bfr[0][2]);
                mma16816(acc[mi][2], af[mi], &bfr[1][0]);
                mma16816(acc[mi][3], af[mi], &bfr[1][2]);
            }
        }
    }
#pragma unroll
    for (int mi = 0; mi < 4; mi++) {
        int row = m0 + wm + mi * 16 + g;
#pragma unroll
        for (int ni = 0; ni < 4; ni++) {
            int col = n0 + wn + ni * 8 + 2 * tg;
            *(float2*)&out[(size_t)row * DD + col] =
                make_float2(acc[mi][ni][0], acc[mi][ni][1]);
            *(float2*)&out[(size_t)(row + 8) * DD + col] =
                make_float2(acc[mi][ni][2], acc[mi][ni][3]);
        }
    }
}

// ======= L6: attn — bias MLP + softmax -> packed attn weights (triplet) =======
__global__ __launch_bounds__(256)
void attn2_kernel(const float* __restrict__ dist,
                  const float* __restrict__ W1, const float* __restrict__ b1,
                  const float* __restrict__ W2, const float* __restrict__ b2) {
    __shared__ __align__(16) float w2_sh[HH][256];
    __shared__ __align__(16) float hid_sh[NC][260];
    __shared__ float qk_sh[NM];
    __shared__ float sc_sh[NM];
    __shared__ float aw_sh[NM];
    __shared__ float dj_sh[NC];
    __shared__ int   sel_sh[NC];
    __shared__ int   ego_sh;

    int tok = blockIdx.x;
    int b = tok >> 9, i = tok & 511;
    int t = threadIdx.x;
    int wid = t >> 5, lane = t & 31;

    if (t == 0) {
        int K = g_K;
        int cnt = 0;
        for (int c = 0; c < NC; c++) {
            int idx = g_cand_idx[b][c];
            int s = (idx != i && cnt < K) ? 1 : 0;
            sel_sh[c] = s;
            cnt += s;
        }
        int e = -1, ec = g_ego_cnt;
        for (int q = 0; q < ec; q++)
            if (g_ego_idx[q] == tok) e = q;
        ego_sh = e;
    }
    if (t < NC) dj_sh[t] = g_cand_dist[b][t];
    {
        float4* w2v = (float4*)w2_sh;
        const float4* w2g = (const float4*)W2;
#pragma unroll
        for (int v = 0; v < 4; v++)
            w2v[t + v * 256] = w2g[t + v * 256];
    }
    if (t < NM) {
        qk_sh[t] = g_spart[(size_t)tok * NMP + t]
                 + g_spart[(size_t)NTOK * NMP + (size_t)tok * NMP + t]
                 + g_spart[2 * (size_t)NTOK * NMP + (size_t)tok * NMP + t]
                 + g_spart[3 * (size_t)NTOK * NMP + (size_t)tok * NMP + t];
    }
    __syncthreads();

    float d_i = dist[tok];
    for (int v = t; v < NC * 256; v += 256) {
        int k = v >> 8, r = v & 255;
        float h = d_i * W1[r * 2] + dj_sh[k] * W1[r * 2 + 1] + b1[r];
        hid_sh[k][r] = fmaxf(h, 0.f);
    }
    __syncthreads();

    int ego = ego_sh;
    for (int p = wid; p < NM; p += 8) {
        int h = p / NC, c = p - h * NC;
        float4 ha = *(const float4*)&hid_sh[c][lane * 4];
        float4 wa = *(const float4*)&w2_sh[h][lane * 4];
        float4 hb = *(const float4*)&hid_sh[c][128 + lane * 4];
        float4 wb = *(const float4*)&w2_sh[h][128 + lane * 4];
        float part = ha.x * wa.x + ha.y * wa.y + ha.z * wa.z + ha.w * wa.w
                   + hb.x * wb.x + hb.y * wb.y + hb.z * wb.z + hb.w * wb.w;
        if (ego >= 0) {
            float2 qv = *(const float2*)&g_Qeq[(size_t)ego * DD + h * HDIM + lane * 2];
            float2 kv = *(const float2*)&g_Kc[(size_t)(b * NC + c) * DD + h * HDIM + lane * 2];
            part += 0.125f * (qv.x * kv.x + qv.y * kv.y);
        }
#pragma unroll
        for (int s = 16; s > 0; s >>= 1)
            part += __shfl_xor_sync(0xFFFFFFFFu, part, s);
        if (lane == 0) {
            float qk = (ego >= 0) ? 0.f : 0.125f * qk_sh[p];
            sc_sh[p] = part + qk + b2[h];
        }
    }
    __syncthreads();

    if (t < HH) {
        float mx = -1e30f;
        for (int c = 0; c < NC; c++)
            if (sel_sh[c]) mx = fmaxf(mx, sc_sh[t * NC + c]);
        float sm = 0.f;
        float ev[NC];
#pragma unroll
        for (int c = 0; c < NC; c++) {
            float e = sel_sh[c] ? expf(sc_sh[t * NC + c] - mx) : 0.f;
            ev[c] = e; sm += e;
        }
        float inv = 1.f / sm;
#pragma unroll
        for (int c = 0; c < NC; c++) aw_sh[t * NC + c] = ev[c] * inv;
    }
    __syncthreads();

    // triplet layout: k = 3*m + copy, copies [hi, lo, hi]
    size_t base = (size_t)tok * KOUT;
    if (t < NM) {
        float w = aw_sh[t];
        __nv_bfloat16 hh = __float2bfloat16(w);
        __nv_bfloat16 ll = __float2bfloat16(w - __bfloat162float(hh));
        g_AW[base + 3 * t]     = hh;
        g_AW[base + 3 * t + 1] = ll;
        g_AW[base + 3 * t + 2] = hh;
    } else if (t < NM + 16) {
        g_AW[base + 624 + (t - NM)] = __float2bfloat16(0.f);
    }
}

// ================= launch =================
extern "C" void kernel_launch(void* const* d_in, const int* in_sizes, int n_in,
                              void* d_out, int out_size) {
    const float* tokens = (const float*)d_in[0];
    const float* dist   = (const float*)d_in[1];
    const int*   mask   = (const int*)d_in[2];
    const float* speed  = (const float*)d_in[3];
    const float* Wq     = (const float*)d_in[4];
    const float* Wk     = (const float*)d_in[5];
    const float* Wv     = (const float*)d_in[6];
    const float* Weq    = (const float*)d_in[7];
    const float* Wo     = (const float*)d_in[8];
    const float* W1     = (const float*)d_in[9];
    const float* b1     = (const float*)d_in[10];
    const float* W2     = (const float*)d_in[11];
    const float* b2     = (const float*)d_in[12];
    float*       out    = (float*)d_out;

    __nv_bfloat16 *pAbf, *pMbf, *pPtbf, *pAW;
    cudaGetSymbolAddress((void**)&pAbf,  g_Abf);
    cudaGetSymbolAddress((void**)&pMbf,  g_Mbf);
    cudaGetSymbolAddress((void**)&pPtbf, g_Ptbf);
    cudaGetSymbolAddress((void**)&pAW,   g_AW);

    cudaFuncSetAttribute(scores_gemm_kernel, cudaFuncAttributeMaxDynamicSharedMemorySize, SMTOT);
    cudaFuncSetAttribute(out_gemm_kernel,    cudaFuncAttributeMaxDynamicSharedMemorySize, SMTOT);

    // 1: pack X + candidates + K + ego list + M/P padding
    prep_kernel<<<2472, 256>>>(tokens, dist, speed, mask, pAbf);
    // 2: candidate K/V (fp32 splitK) + ego Qeq rows
    cand_ego_kernel<<<dim3(16, 2, 10), 256>>>(tokens, Wk, Wv, Weq);
    // 3: reduce K/V partials
    cand_reduce_kernel<<<256, 256>>>();
    // 4: M / P^T precompute (R13 structure + triplet P stores) (PROFILED SLOT)
    mp_pre_kernel<<<2048, 256>>>(Wq, Wo);
    // 5: scores GEMM (splitK=4)
    scores_gemm_kernel<<<dim3(2, 32, 4), 256, SMTOT>>>(pAbf, pMbf);
    // 6: bias + softmax -> packed attn weights (triplet)
    attn2_kernel<<<NTOK, 256>>>(dist, W1, b1, W2, b2);
    // 7: out = attnW @ P^T
    out_gemm_kernel<<<dim3(8, 32), 256, SMTOT>>>(pAW, pPtbf, out);
}